// round 8
// baseline (speedup 1.0000x reference)
#include <cuda_runtime.h>

#define N_NODES 200000
#define N_EDGES 6400000
#define IN_DIM  1433
#define HID     16
#define OUTD    7
#define OUTP    8
#define SCAN_BLOCKS ((N_NODES + 255) / 256)   // 782
#define KC       32                            // k-chunk for gemm1
#define NCHUNK  ((IN_DIM + KC - 1) / KC)       // 45

typedef unsigned long long ull;

// -------- scratch (device globals; no runtime allocation allowed) --------
__device__ float g_XW1[N_NODES * HID];          // 12.8 MB  X @ W1
__device__ float g_H  [N_NODES * HID];          // 12.8 MB  L @ (X W1)
__device__ float g_HW2[N_NODES * OUTP];         //  6.4 MB  relu(H+b1) @ W2, padded to 8
__device__ int   g_cnt   [N_NODES];             // per-row edge count
__device__ int   g_rowptr[N_NODES + 1];         // CSR row pointers
__device__ int   g_pos   [N_NODES];             // scatter cursors
__device__ int   g_bsum  [SCAN_BLOCKS];
__device__ int   g_boff  [SCAN_BLOCKS];
__device__ ull   g_edge  [N_EDGES];             // 51.2 MB packed (val, col) sorted by row

// packed fp32x2 helpers (FFMA2: 2 fp32 FMAs / instr, full fp32 precision)
__device__ __forceinline__ ull pack2(float lo, float hi) {
    ull v; asm("mov.b64 %0, {%1, %2};" : "=l"(v) : "f"(lo), "f"(hi)); return v;
}
__device__ __forceinline__ void ffma2(ull& d, ull a, ull b) {
    asm("fma.rn.f32x2 %0, %1, %2, %3;" : "=l"(d) : "l"(a), "l"(b), "l"(d));
}

// -------- zero the row counters --------
__global__ void zero_kernel() {
    int i = blockIdx.x * blockDim.x + threadIdx.x;
    if (i < N_NODES) g_cnt[i] = 0;
}

// -------- count edges per row --------
__global__ void __launch_bounds__(256) count_kernel(const int* __restrict__ erow) {
    int q = blockIdx.x * 256 + threadIdx.x;
    if (q >= N_EDGES / 4) return;
    int4 r4 = ((const int4*)erow)[q];
    asm volatile("red.global.add.u32 [%0], 1;" :: "l"(&g_cnt[r4.x]) : "memory");
    asm volatile("red.global.add.u32 [%0], 1;" :: "l"(&g_cnt[r4.y]) : "memory");
    asm volatile("red.global.add.u32 [%0], 1;" :: "l"(&g_cnt[r4.z]) : "memory");
    asm volatile("red.global.add.u32 [%0], 1;" :: "l"(&g_cnt[r4.w]) : "memory");
}

// -------- exclusive scan of g_cnt -> g_rowptr (3-phase) --------
__global__ void __launch_bounds__(256) scan1_kernel() {
    __shared__ int s[256];
    int t = threadIdx.x;
    int i = blockIdx.x * 256 + t;
    int x = (i < N_NODES) ? g_cnt[i] : 0;
    s[t] = x;
    __syncthreads();
#pragma unroll
    for (int d = 1; d < 256; d <<= 1) {
        int y = (t >= d) ? s[t - d] : 0;
        __syncthreads();
        s[t] += y;
        __syncthreads();
    }
    if (i < N_NODES) g_rowptr[i] = s[t] - x;
    if (t == 255) g_bsum[blockIdx.x] = s[t];
}

// -------- GEMM1  g_XW1 = X @ W1   (200000 x 1433 x 16) --------
// 256 threads, 256 rows/block, 1 row/thread. Plain LDG staging with MODERATE
// unroll (4): ~regs<=48 -> ~5 blocks/SM, LDG at its 1.82cyc floor (no LDGSTS
// 8cyc tax, no 244-reg batch). FFMA2 inner loop.
__global__ void __launch_bounds__(256) gemm1_kernel(const float* __restrict__ X,
                                                    const float* __restrict__ W1) {
    __shared__ float As[256][KC + 1];                    // 33 coprime 32: conflict-free
    __shared__ __align__(16) float Ws[KC][16];

    const int t    = threadIdx.x;
    const int row0 = blockIdx.x * 256;
    const bool full_rows = (row0 + 256 <= N_NODES);

    ull acc[8];
#pragma unroll
    for (int j = 0; j < 8; j++) acc[j] = 0ull;

    for (int c = 0; c < NCHUNK; c++) {
        const int kc = c * KC;
        const bool fullk = (kc + KC <= IN_DIM);

        // stage W chunk: KC x 16 = 512 floats, 2 per thread
#pragma unroll
        for (int s = 0; s < 2; s++) {
            int flat = t + 256 * s;
            int k = flat >> 4, j = flat & 15;
            Ws[k][j] = (fullk || kc + k < IN_DIM) ? W1[(kc + k) * HID + j] : 0.f;
        }
        // stage A tile: 256 x 32 floats, 32 per thread, coalesced
        // (consecutive t -> consecutive k within a row; warp covers 4 rows x 32)
        if (full_rows && fullk) {
#pragma unroll 4
            for (int s = 0; s < 32; s++) {
                int flat = t + 256 * s;
                int r = flat >> 5, k = flat & 31;
                As[r][k] = X[(long)(row0 + r) * IN_DIM + (kc + k)];
            }
        } else {
#pragma unroll 4
            for (int s = 0; s < 32; s++) {
                int flat = t + 256 * s;
                int r = flat >> 5, k = flat & 31;
                int gr = row0 + r, gk = kc + k;
                As[r][k] = (gr < N_NODES && gk < IN_DIM)
                             ? X[(long)gr * IN_DIM + gk] : 0.f;
            }
        }
        __syncthreads();

#pragma unroll 8
        for (int k = 0; k < KC; k++) {
            const ulonglong2* wp = (const ulonglong2*)&Ws[k][0];
            ulonglong2 wa = wp[0], wb = wp[1], wc = wp[2], wd = wp[3];
            float a = As[t][k];
            ull ap = pack2(a, a);
            ffma2(acc[0], ap, wa.x); ffma2(acc[1], ap, wa.y);
            ffma2(acc[2], ap, wb.x); ffma2(acc[3], ap, wb.y);
            ffma2(acc[4], ap, wc.x); ffma2(acc[5], ap, wc.y);
            ffma2(acc[6], ap, wd.x); ffma2(acc[7], ap, wd.y);
        }
        __syncthreads();
    }

    int r = row0 + t;
    if (r < N_NODES) {
        ulonglong2* d = (ulonglong2*)&g_XW1[r * HID];
        d[0] = make_ulonglong2(acc[0], acc[1]);
        d[1] = make_ulonglong2(acc[2], acc[3]);
        d[2] = make_ulonglong2(acc[4], acc[5]);
        d[3] = make_ulonglong2(acc[6], acc[7]);
    }
}

__global__ void __launch_bounds__(1024) scan2_kernel() {
    __shared__ int s[1024];
    int t = threadIdx.x;
    int x = (t < SCAN_BLOCKS) ? g_bsum[t] : 0;
    s[t] = x;
    __syncthreads();
#pragma unroll
    for (int d = 1; d < 1024; d <<= 1) {
        int y = (t >= d) ? s[t - d] : 0;
        __syncthreads();
        s[t] += y;
        __syncthreads();
    }
    if (t < SCAN_BLOCKS) g_boff[t] = s[t] - x;
}

__global__ void __launch_bounds__(256) scan3_kernel() {
    int i = blockIdx.x * 256 + threadIdx.x;
    if (i < N_NODES) {
        int v = g_rowptr[i] + g_boff[blockIdx.x];
        g_rowptr[i] = v;
        g_pos[i] = v;
    }
    if (i == 0) g_rowptr[N_NODES] = N_EDGES;
}

// -------- scatter edges into row-sorted packed array --------
__global__ void __launch_bounds__(256) scatter_kernel(const int*   __restrict__ erow,
                                                      const int*   __restrict__ ecol,
                                                      const float* __restrict__ evals) {
    int q = blockIdx.x * 256 + threadIdx.x;
    if (q >= N_EDGES / 4) return;
    int4   r4 = ((const int4*)erow)[q];
    int4   c4 = ((const int4*)ecol)[q];
    float4 v4 = ((const float4*)evals)[q];
    int   rr[4] = {r4.x, r4.y, r4.z, r4.w};
    int   cc[4] = {c4.x, c4.y, c4.z, c4.w};
    float vv[4] = {v4.x, v4.y, v4.z, v4.w};
#pragma unroll
    for (int i = 0; i < 4; i++) {
        int p = atomicAdd(&g_pos[rr[i]], 1);
        g_edge[p] = ((ull)__float_as_uint(vv[i]) << 32) | (unsigned)cc[i];
    }
}

// -------- SPMM1: warp per row, lanes 0-15 even edges / 16-31 odd, 4x unroll --------
__global__ void __launch_bounds__(256) spmm1_kernel() {
    int warp = (blockIdx.x * 256 + threadIdx.x) >> 5;
    if (warp >= N_NODES) return;
    int lane = threadIdx.x & 31;
    int half = lane >> 4;
    int dim  = lane & 15;

    int start = g_rowptr[warp];
    int end   = g_rowptr[warp + 1];

    float acc = 0.f;
    int i = start + half;
    for (; i + 6 < end; i += 8) {
        ull e0 = g_edge[i];
        ull e1 = g_edge[i + 2];
        ull e2 = g_edge[i + 4];
        ull e3 = g_edge[i + 6];
        int c0 = (int)(unsigned)e0;  float v0 = __uint_as_float((unsigned)(e0 >> 32));
        int c1 = (int)(unsigned)e1;  float v1 = __uint_as_float((unsigned)(e1 >> 32));
        int c2 = (int)(unsigned)e2;  float v2 = __uint_as_float((unsigned)(e2 >> 32));
        int c3 = (int)(unsigned)e3;  float v3 = __uint_as_float((unsigned)(e3 >> 32));
        float x0 = g_XW1[c0 * HID + dim];
        float x1 = g_XW1[c1 * HID + dim];
        float x2 = g_XW1[c2 * HID + dim];
        float x3 = g_XW1[c3 * HID + dim];
        acc = fmaf(v0, x0, acc);
        acc = fmaf(v1, x1, acc);
        acc = fmaf(v2, x2, acc);
        acc = fmaf(v3, x3, acc);
    }
    for (; i < end; i += 2) {
        ull e0 = g_edge[i];
        int c0 = (int)(unsigned)e0;  float v0 = __uint_as_float((unsigned)(e0 >> 32));
        acc = fmaf(v0, g_XW1[c0 * HID + dim], acc);
    }
    acc += __shfl_xor_sync(0xffffffff, acc, 16);
    if (half == 0) g_H[warp * HID + dim] = acc;
}

// -------- GEMM2  g_HW2 = relu(g_H + b1) @ W2, padded to 8 cols --------
__global__ void __launch_bounds__(256) gemm2_kernel(const float* __restrict__ b1,
                                                    const float* __restrict__ W2) {
    __shared__ float sW2[HID * OUTD];
    __shared__ float sb1[HID];
    int t = threadIdx.x;
    if (t < HID * OUTD) sW2[t] = W2[t];
    if (t < HID)        sb1[t] = b1[t];
    __syncthreads();

    int i = blockIdx.x * 256 + t;
    if (i >= N_NODES) return;

    const float4* hp = (const float4*)&g_H[i * HID];
    float h[16];
    *(float4*)&h[0]  = hp[0]; *(float4*)&h[4]  = hp[1];
    *(float4*)&h[8]  = hp[2]; *(float4*)&h[12] = hp[3];
#pragma unroll
    for (int j = 0; j < 16; j++) h[j] = fmaxf(h[j] + sb1[j], 0.f);

    float o[OUTP];
#pragma unroll
    for (int c = 0; c < OUTD; c++) {
        float s = 0.f;
#pragma unroll
        for (int j = 0; j < HID; j++) s = fmaf(h[j], sW2[j * OUTD + c], s);
        o[c] = s;
    }
    o[7] = 0.f;

    float4* d = (float4*)&g_HW2[i * OUTP];
    d[0] = *(float4*)&o[0];
    d[1] = *(float4*)&o[4];
}

// -------- SPMM2 + bias fused --------
__global__ void __launch_bounds__(256) spmm2_kernel(const float* __restrict__ b2,
                                                    float* __restrict__ out) {
    int warp = (blockIdx.x * 256 + threadIdx.x) >> 5;
    if (warp >= N_NODES) return;
    int lane = threadIdx.x & 31;
    int sub  = lane >> 3;
    int dim  = lane & 7;

    int start = g_rowptr[warp];
    int end   = g_rowptr[warp + 1];

    float acc = 0.f;
    int i = start + sub;
    for (; i + 12 < end; i += 16) {
        ull e0 = g_edge[i];
        ull e1 = g_edge[i + 4];
        ull e2 = g_edge[i + 8];
        ull e3 = g_edge[i + 12];
        int c0 = (int)(unsigned)e0;  float v0 = __uint_as_float((unsigned)(e0 >> 32));
        int c1 = (int)(unsigned)e1;  float v1 = __uint_as_float((unsigned)(e1 >> 32));
        int c2 = (int)(unsigned)e2;  float v2 = __uint_as_float((unsigned)(e2 >> 32));
        int c3 = (int)(unsigned)e3;  float v3 = __uint_as_float((unsigned)(e3 >> 32));
        float x0 = g_HW2[c0 * OUTP + dim];
        float x1 = g_HW2[c1 * OUTP + dim];
        float x2 = g_HW2[c2 * OUTP + dim];
        float x3 = g_HW2[c3 * OUTP + dim];
        acc = fmaf(v0, x0, acc);
        acc = fmaf(v1, x1, acc);
        acc = fmaf(v2, x2, acc);
        acc = fmaf(v3, x3, acc);
    }
    for (; i < end; i += 4) {
        ull e0 = g_edge[i];
        int c0 = (int)(unsigned)e0;  float v0 = __uint_as_float((unsigned)(e0 >> 32));
        acc = fmaf(v0, g_HW2[c0 * OUTP + dim], acc);
    }
    acc += __shfl_xor_sync(0xffffffff, acc, 8);
    acc += __shfl_xor_sync(0xffffffff, acc, 16);
    if (lane < OUTD) out[warp * OUTD + lane] = acc + b2[lane];
}

extern "C" void kernel_launch(void* const* d_in, const int* in_sizes, int n_in,
                              void* d_out, int out_size) {
    const float* feature = (const float*)d_in[0];
    const int*   erow    = (const int*)  d_in[1];
    const int*   ecol    = (const int*)  d_in[2];
    const float* evals   = (const float*)d_in[3];
    const float* W1      = (const float*)d_in[4];
    const float* b1      = (const float*)d_in[5];
    const float* W2      = (const float*)d_in[6];
    const float* b2      = (const float*)d_in[7];
    float* out = (float*)d_out;

    int quad_blocks = (N_EDGES / 4 + 255) / 256;           // 6250
    int node_blocks = (N_NODES + 255) / 256;               // 782
    int warp_blocks = (N_NODES * 32 + 255) / 256;          // 25000

    // order keeps gemm1 at launch index 3 -> the kernel ncu captures
    zero_kernel<<<node_blocks, 256>>>();                   // 0
    count_kernel<<<quad_blocks, 256>>>(erow);              // 1
    scan1_kernel<<<SCAN_BLOCKS, 256>>>();                  // 2
    gemm1_kernel<<<node_blocks, 256>>>(feature, W1);       // 3  <- profiled
    scan2_kernel<<<1, 1024>>>();                           // 4
    scan3_kernel<<<SCAN_BLOCKS, 256>>>();                  // 5
    scatter_kernel<<<quad_blocks, 256>>>(erow, ecol, evals);
    spmm1_kernel<<<warp_blocks, 256>>>();
    gemm2_kernel<<<node_blocks, 256>>>(b1, W2);
    spmm2_kernel<<<warp_blocks, 256>>>(b2, out);
}

// round 9
// speedup vs baseline: 1.0655x; 1.0655x over previous
#include <cuda_runtime.h>

#define N_NODES 200000
#define N_EDGES 6400000
#define IN_DIM  1433
#define HID     16
#define OUTD    7
#define OUTP    8
#define SCAN_BLOCKS ((N_NODES + 255) / 256)   // 782

typedef unsigned long long ull;

// -------- scratch (device globals; no runtime allocation allowed) --------
__device__ float g_XW1[N_NODES * HID];          // 12.8 MB  X @ W1
__device__ float g_H  [N_NODES * HID];          // 12.8 MB  L @ (X W1)
__device__ float g_HW2[N_NODES * OUTP];         //  6.4 MB  relu(H+b1) @ W2, padded to 8
__device__ int   g_cnt   [N_NODES];             // per-row edge count
__device__ int   g_rowptr[N_NODES + 1];         // CSR row pointers
__device__ int   g_pos   [N_NODES];             // scatter cursors
__device__ int   g_bsum  [SCAN_BLOCKS];
__device__ int   g_boff  [SCAN_BLOCKS];
__device__ ull   g_edge  [N_EDGES];             // 51.2 MB packed (val, col) sorted by row

// packed fp32x2 helpers (FFMA2: 2 fp32 FMAs / instr, full fp32 precision)
__device__ __forceinline__ ull pack2(float lo, float hi) {
    ull v; asm("mov.b64 %0, {%1, %2};" : "=l"(v) : "f"(lo), "f"(hi)); return v;
}
__device__ __forceinline__ void ffma2(ull& d, ull a, ull b) {
    asm("fma.rn.f32x2 %0, %1, %2, %3;" : "=l"(d) : "l"(a), "l"(b), "l"(d));
}

// -------- zero the row counters --------
__global__ void zero_kernel() {
    int i = blockIdx.x * blockDim.x + threadIdx.x;
    if (i < N_NODES) g_cnt[i] = 0;
}

// -------- count edges per row --------
__global__ void __launch_bounds__(256) count_kernel(const int* __restrict__ erow) {
    int q = blockIdx.x * 256 + threadIdx.x;
    if (q >= N_EDGES / 4) return;
    int4 r4 = ((const int4*)erow)[q];
    asm volatile("red.global.add.u32 [%0], 1;" :: "l"(&g_cnt[r4.x]) : "memory");
    asm volatile("red.global.add.u32 [%0], 1;" :: "l"(&g_cnt[r4.y]) : "memory");
    asm volatile("red.global.add.u32 [%0], 1;" :: "l"(&g_cnt[r4.z]) : "memory");
    asm volatile("red.global.add.u32 [%0], 1;" :: "l"(&g_cnt[r4.w]) : "memory");
}

// -------- exclusive scan of g_cnt -> g_rowptr (3-phase) --------
__global__ void __launch_bounds__(256) scan1_kernel() {
    __shared__ int s[256];
    int t = threadIdx.x;
    int i = blockIdx.x * 256 + t;
    int x = (i < N_NODES) ? g_cnt[i] : 0;
    s[t] = x;
    __syncthreads();
#pragma unroll
    for (int d = 1; d < 256; d <<= 1) {
        int y = (t >= d) ? s[t - d] : 0;
        __syncthreads();
        s[t] += y;
        __syncthreads();
    }
    if (i < N_NODES) g_rowptr[i] = s[t] - x;
    if (t == 255) g_bsum[blockIdx.x] = s[t];
}

// -------- GEMM1  g_XW1 = X @ W1   (200000 x 1433 x 16) --------
// R6 configuration restored (128 threads, 256 rows/block, 2 rows/thread,
// FFMA2 inner loop). ONE change vs R6: A-staging unroll 64 -> 16, cutting the
// register batch (244 -> ~110 regs) so ~4 blocks/SM co-reside (16 warps vs 8)
// while each warp still keeps 16 LDGs in flight. In-flight bytes/SM:
// 16 warps x 16 x 128B = 32KB > 23KB needed to cover DRAM latency.
__global__ void __launch_bounds__(128) gemm1_kernel(const float* __restrict__ X,
                                                    const float* __restrict__ W1) {
    __shared__ __align__(16) float As[256][33];
    __shared__ __align__(16) float Ws[32][16];

    const int t    = threadIdx.x;
    const int row0 = blockIdx.x * 256;
    const bool edge = (row0 + 256 > N_NODES);

    ull acc0[8], acc1[8];
#pragma unroll
    for (int j = 0; j < 8; j++) { acc0[j] = 0ull; acc1[j] = 0ull; }

    for (int kc = 0; kc < IN_DIM; kc += 32) {
        const bool fullk = (kc + 32 <= IN_DIM);
        // stage W1 chunk: 32x16
#pragma unroll
        for (int s = 0; s < 4; s++) {
            int flat = t + 128 * s;
            int k = flat >> 4, j = flat & 15;
            Ws[k][j] = (fullk || kc + k < IN_DIM) ? W1[(kc + k) * HID + j] : 0.f;
        }
        // stage A tile: 256x32, coalesced; unroll 16 -> 16 LDGs in flight/warp
        if (!edge && fullk) {
#pragma unroll 16
            for (int s = 0; s < 64; s++) {
                int flat = t + 128 * s;
                int r = flat >> 5, k = flat & 31;
                As[r][k] = X[(long)(row0 + r) * IN_DIM + (kc + k)];
            }
        } else {
#pragma unroll 16
            for (int s = 0; s < 64; s++) {
                int flat = t + 128 * s;
                int r = flat >> 5, k = flat & 31;
                int gr = row0 + r, gk = kc + k;
                As[r][k] = (gr < N_NODES && gk < IN_DIM)
                             ? X[(long)gr * IN_DIM + gk] : 0.f;
            }
        }
        __syncthreads();

#pragma unroll 4
        for (int k = 0; k < 32; k++) {
            const ulonglong2* wp = (const ulonglong2*)&Ws[k][0];
            ulonglong2 wa = wp[0], wb = wp[1], wc = wp[2], wd = wp[3];
            float a0 = As[t][k];
            float a1 = As[t + 128][k];
            ull a0p = pack2(a0, a0);
            ull a1p = pack2(a1, a1);
            ffma2(acc0[0], a0p, wa.x); ffma2(acc0[1], a0p, wa.y);
            ffma2(acc0[2], a0p, wb.x); ffma2(acc0[3], a0p, wb.y);
            ffma2(acc0[4], a0p, wc.x); ffma2(acc0[5], a0p, wc.y);
            ffma2(acc0[6], a0p, wd.x); ffma2(acc0[7], a0p, wd.y);
            ffma2(acc1[0], a1p, wa.x); ffma2(acc1[1], a1p, wa.y);
            ffma2(acc1[2], a1p, wb.x); ffma2(acc1[3], a1p, wb.y);
            ffma2(acc1[4], a1p, wc.x); ffma2(acc1[5], a1p, wc.y);
            ffma2(acc1[6], a1p, wd.x); ffma2(acc1[7], a1p, wd.y);
        }
        __syncthreads();
    }

    int r0 = row0 + t, r1 = row0 + t + 128;
    if (r0 < N_NODES) {
        ulonglong2* d = (ulonglong2*)&g_XW1[r0 * HID];
        d[0] = make_ulonglong2(acc0[0], acc0[1]);
        d[1] = make_ulonglong2(acc0[2], acc0[3]);
        d[2] = make_ulonglong2(acc0[4], acc0[5]);
        d[3] = make_ulonglong2(acc0[6], acc0[7]);
    }
    if (r1 < N_NODES) {
        ulonglong2* d = (ulonglong2*)&g_XW1[r1 * HID];
        d[0] = make_ulonglong2(acc1[0], acc1[1]);
        d[1] = make_ulonglong2(acc1[2], acc1[3]);
        d[2] = make_ulonglong2(acc1[4], acc1[5]);
        d[3] = make_ulonglong2(acc1[6], acc1[7]);
    }
}

__global__ void __launch_bounds__(1024) scan2_kernel() {
    __shared__ int s[1024];
    int t = threadIdx.x;
    int x = (t < SCAN_BLOCKS) ? g_bsum[t] : 0;
    s[t] = x;
    __syncthreads();
#pragma unroll
    for (int d = 1; d < 1024; d <<= 1) {
        int y = (t >= d) ? s[t - d] : 0;
        __syncthreads();
        s[t] += y;
        __syncthreads();
    }
    if (t < SCAN_BLOCKS) g_boff[t] = s[t] - x;
}

__global__ void __launch_bounds__(256) scan3_kernel() {
    int i = blockIdx.x * 256 + threadIdx.x;
    if (i < N_NODES) {
        int v = g_rowptr[i] + g_boff[blockIdx.x];
        g_rowptr[i] = v;
        g_pos[i] = v;
    }
    if (i == 0) g_rowptr[N_NODES] = N_EDGES;
}

// -------- scatter edges into row-sorted packed array --------
__global__ void __launch_bounds__(256) scatter_kernel(const int*   __restrict__ erow,
                                                      const int*   __restrict__ ecol,
                                                      const float* __restrict__ evals) {
    int q = blockIdx.x * 256 + threadIdx.x;
    if (q >= N_EDGES / 4) return;
    int4   r4 = ((const int4*)erow)[q];
    int4   c4 = ((const int4*)ecol)[q];
    float4 v4 = ((const float4*)evals)[q];
    int   rr[4] = {r4.x, r4.y, r4.z, r4.w};
    int   cc[4] = {c4.x, c4.y, c4.z, c4.w};
    float vv[4] = {v4.x, v4.y, v4.z, v4.w};
#pragma unroll
    for (int i = 0; i < 4; i++) {
        int p = atomicAdd(&g_pos[rr[i]], 1);
        g_edge[p] = ((ull)__float_as_uint(vv[i]) << 32) | (unsigned)cc[i];
    }
}

// -------- SPMM1: warp per row, lanes 0-15 even edges / 16-31 odd, 4x unroll --------
__global__ void __launch_bounds__(256) spmm1_kernel() {
    int warp = (blockIdx.x * 256 + threadIdx.x) >> 5;
    if (warp >= N_NODES) return;
    int lane = threadIdx.x & 31;
    int half = lane >> 4;
    int dim  = lane & 15;

    int start = g_rowptr[warp];
    int end   = g_rowptr[warp + 1];

    float acc = 0.f;
    int i = start + half;
    for (; i + 6 < end; i += 8) {
        ull e0 = g_edge[i];
        ull e1 = g_edge[i + 2];
        ull e2 = g_edge[i + 4];
        ull e3 = g_edge[i + 6];
        int c0 = (int)(unsigned)e0;  float v0 = __uint_as_float((unsigned)(e0 >> 32));
        int c1 = (int)(unsigned)e1;  float v1 = __uint_as_float((unsigned)(e1 >> 32));
        int c2 = (int)(unsigned)e2;  float v2 = __uint_as_float((unsigned)(e2 >> 32));
        int c3 = (int)(unsigned)e3;  float v3 = __uint_as_float((unsigned)(e3 >> 32));
        float x0 = g_XW1[c0 * HID + dim];
        float x1 = g_XW1[c1 * HID + dim];
        float x2 = g_XW1[c2 * HID + dim];
        float x3 = g_XW1[c3 * HID + dim];
        acc = fmaf(v0, x0, acc);
        acc = fmaf(v1, x1, acc);
        acc = fmaf(v2, x2, acc);
        acc = fmaf(v3, x3, acc);
    }
    for (; i < end; i += 2) {
        ull e0 = g_edge[i];
        int c0 = (int)(unsigned)e0;  float v0 = __uint_as_float((unsigned)(e0 >> 32));
        acc = fmaf(v0, g_XW1[c0 * HID + dim], acc);
    }
    acc += __shfl_xor_sync(0xffffffff, acc, 16);
    if (half == 0) g_H[warp * HID + dim] = acc;
}

// -------- GEMM2  g_HW2 = relu(g_H + b1) @ W2, padded to 8 cols --------
__global__ void __launch_bounds__(256) gemm2_kernel(const float* __restrict__ b1,
                                                    const float* __restrict__ W2) {
    __shared__ float sW2[HID * OUTD];
    __shared__ float sb1[HID];
    int t = threadIdx.x;
    if (t < HID * OUTD) sW2[t] = W2[t];
    if (t < HID)        sb1[t] = b1[t];
    __syncthreads();

    int i = blockIdx.x * 256 + t;
    if (i >= N_NODES) return;

    const float4* hp = (const float4*)&g_H[i * HID];
    float h[16];
    *(float4*)&h[0]  = hp[0]; *(float4*)&h[4]  = hp[1];
    *(float4*)&h[8]  = hp[2]; *(float4*)&h[12] = hp[3];
#pragma unroll
    for (int j = 0; j < 16; j++) h[j] = fmaxf(h[j] + sb1[j], 0.f);

    float o[OUTP];
#pragma unroll
    for (int c = 0; c < OUTD; c++) {
        float s = 0.f;
#pragma unroll
        for (int j = 0; j < HID; j++) s = fmaf(h[j], sW2[j * OUTD + c], s);
        o[c] = s;
    }
    o[7] = 0.f;

    float4* d = (float4*)&g_HW2[i * OUTP];
    d[0] = *(float4*)&o[0];
    d[1] = *(float4*)&o[4];
}

// -------- SPMM2 + bias fused --------
__global__ void __launch_bounds__(256) spmm2_kernel(const float* __restrict__ b2,
                                                    float* __restrict__ out) {
    int warp = (blockIdx.x * 256 + threadIdx.x) >> 5;
    if (warp >= N_NODES) return;
    int lane = threadIdx.x & 31;
    int sub  = lane >> 3;
    int dim  = lane & 7;

    int start = g_rowptr[warp];
    int end   = g_rowptr[warp + 1];

    float acc = 0.f;
    int i = start + sub;
    for (; i + 12 < end; i += 16) {
        ull e0 = g_edge[i];
        ull e1 = g_edge[i + 4];
        ull e2 = g_edge[i + 8];
        ull e3 = g_edge[i + 12];
        int c0 = (int)(unsigned)e0;  float v0 = __uint_as_float((unsigned)(e0 >> 32));
        int c1 = (int)(unsigned)e1;  float v1 = __uint_as_float((unsigned)(e1 >> 32));
        int c2 = (int)(unsigned)e2;  float v2 = __uint_as_float((unsigned)(e2 >> 32));
        int c3 = (int)(unsigned)e3;  float v3 = __uint_as_float((unsigned)(e3 >> 32));
        float x0 = g_HW2[c0 * OUTP + dim];
        float x1 = g_HW2[c1 * OUTP + dim];
        float x2 = g_HW2[c2 * OUTP + dim];
        float x3 = g_HW2[c3 * OUTP + dim];
        acc = fmaf(v0, x0, acc);
        acc = fmaf(v1, x1, acc);
        acc = fmaf(v2, x2, acc);
        acc = fmaf(v3, x3, acc);
    }
    for (; i < end; i += 4) {
        ull e0 = g_edge[i];
        int c0 = (int)(unsigned)e0;  float v0 = __uint_as_float((unsigned)(e0 >> 32));
        acc = fmaf(v0, g_HW2[c0 * OUTP + dim], acc);
    }
    acc += __shfl_xor_sync(0xffffffff, acc, 8);
    acc += __shfl_xor_sync(0xffffffff, acc, 16);
    if (lane < OUTD) out[warp * OUTD + lane] = acc + b2[lane];
}

extern "C" void kernel_launch(void* const* d_in, const int* in_sizes, int n_in,
                              void* d_out, int out_size) {
    const float* feature = (const float*)d_in[0];
    const int*   erow    = (const int*)  d_in[1];
    const int*   ecol    = (const int*)  d_in[2];
    const float* evals   = (const float*)d_in[3];
    const float* W1      = (const float*)d_in[4];
    const float* b1      = (const float*)d_in[5];
    const float* W2      = (const float*)d_in[6];
    const float* b2      = (const float*)d_in[7];
    float* out = (float*)d_out;

    int quad_blocks = (N_EDGES / 4 + 255) / 256;           // 6250
    int node_blocks = (N_NODES + 255) / 256;               // 782
    int warp_blocks = (N_NODES * 32 + 255) / 256;          // 25000

    // order keeps gemm1 at launch index 3 -> the kernel ncu captures
    zero_kernel<<<node_blocks, 256>>>();                   // 0
    count_kernel<<<quad_blocks, 256>>>(erow);              // 1
    scan1_kernel<<<SCAN_BLOCKS, 256>>>();                  // 2
    gemm1_kernel<<<node_blocks, 128>>>(feature, W1);       // 3  <- profiled
    scan2_kernel<<<1, 1024>>>();                           // 4
    scan3_kernel<<<SCAN_BLOCKS, 256>>>();                  // 5
    scatter_kernel<<<quad_blocks, 256>>>(erow, ecol, evals);
    spmm1_kernel<<<warp_blocks, 256>>>();
    gemm2_kernel<<<node_blocks, 256>>>(b1, W2);
    spmm2_kernel<<<warp_blocks, 256>>>(b2, out);
}

// round 10
// speedup vs baseline: 1.1890x; 1.1159x over previous
#include <cuda_runtime.h>

#define N_NODES 200000
#define N_EDGES 6400000
#define IN_DIM  1433
#define HID     16
#define OUTD    7
#define OUTP    8
#define SCAN_BLOCKS ((N_NODES + 255) / 256)   // 782
#define KC       32
#define NCHUNK  ((IN_DIM + KC - 1) / KC)       // 45

typedef unsigned long long ull;

// -------- scratch (device globals; no runtime allocation allowed) --------
__device__ float g_XW1[N_NODES * HID];          // 12.8 MB  X @ W1
__device__ float g_H  [N_NODES * HID];          // 12.8 MB  L @ (X W1)
__device__ float g_HW2[N_NODES * OUTP];         //  6.4 MB  relu(H+b1) @ W2, padded to 8
__device__ int   g_cnt   [N_NODES];
__device__ int   g_rowptr[N_NODES + 1];
__device__ int   g_pos   [N_NODES];
__device__ int   g_bsum  [SCAN_BLOCKS];
__device__ int   g_boff  [SCAN_BLOCKS];
__device__ ull   g_edge  [N_EDGES];             // 51.2 MB packed (val, col) sorted by row

// packed fp32x2 helpers (FFMA2: 2 fp32 FMAs / instr, full fp32 precision)
__device__ __forceinline__ ull pack2(float lo, float hi) {
    ull v; asm("mov.b64 %0, {%1, %2};" : "=l"(v) : "f"(lo), "f"(hi)); return v;
}
__device__ __forceinline__ void ffma2(ull& d, ull a, ull b) {
    asm("fma.rn.f32x2 %0, %1, %2, %3;" : "=l"(d) : "l"(a), "l"(b), "l"(d));
}

// -------- zero the row counters --------
__global__ void zero_kernel() {
    int i = blockIdx.x * blockDim.x + threadIdx.x;
    if (i < N_NODES) g_cnt[i] = 0;
}

// -------- count edges per row --------
__global__ void __launch_bounds__(256) count_kernel(const int* __restrict__ erow) {
    int q = blockIdx.x * 256 + threadIdx.x;
    if (q >= N_EDGES / 4) return;
    int4 r4 = ((const int4*)erow)[q];
    asm volatile("red.global.add.u32 [%0], 1;" :: "l"(&g_cnt[r4.x]) : "memory");
    asm volatile("red.global.add.u32 [%0], 1;" :: "l"(&g_cnt[r4.y]) : "memory");
    asm volatile("red.global.add.u32 [%0], 1;" :: "l"(&g_cnt[r4.z]) : "memory");
    asm volatile("red.global.add.u32 [%0], 1;" :: "l"(&g_cnt[r4.w]) : "memory");
}

// -------- exclusive scan of g_cnt -> g_rowptr (3-phase) --------
__global__ void __launch_bounds__(256) scan1_kernel() {
    __shared__ int s[256];
    int t = threadIdx.x;
    int i = blockIdx.x * 256 + t;
    int x = (i < N_NODES) ? g_cnt[i] : 0;
    s[t] = x;
    __syncthreads();
#pragma unroll
    for (int d = 1; d < 256; d <<= 1) {
        int y = (t >= d) ? s[t - d] : 0;
        __syncthreads();
        s[t] += y;
        __syncthreads();
    }
    if (i < N_NODES) g_rowptr[i] = s[t] - x;
    if (t == 255) g_bsum[blockIdx.x] = s[t];
}

// -------- GEMM1  g_XW1 = X @ W1   (200000 x 1433 x 16) --------
// Software-pipelined: prefetch chunk c+1 into REGISTERS (plain LDG.32,
// coalesced) while computing chunk c from smem. Single smem buffer.
// 256 threads, 256 rows/block, 1 row/thread. Staging regs v[32] keep
// 32 LDGs in flight per warp during the entire compute phase.
__global__ void __launch_bounds__(256) gemm1_kernel(const float* __restrict__ X,
                                                    const float* __restrict__ W1) {
    __shared__ float As[256][KC + 1];                 // stride 33: conflict-free
    __shared__ __align__(16) float Ws[KC][16];

    const int t     = threadIdx.x;
    const int row0  = blockIdx.x * 256;
    const int kk    = t & 31;                         // this thread's fixed k-lane
    const int rbase = t >> 5;                         // first row it stages (of 32, step 8)
    const bool full_rows = (row0 + 256 <= N_NODES);

    float v[32];                                      // staged A values (chunk in regs)
    float wv[2];                                      // staged W values

    ull acc[8];
#pragma unroll
    for (int j = 0; j < 8; j++) acc[j] = 0ull;

    // ---- prefetch helpers ----
    auto prefA = [&](int c) {
        const int kc = c * KC;
        const float* p = X + (long)(row0 + rbase) * IN_DIM + kc + kk;
        if (full_rows && kc + KC <= IN_DIM) {
#pragma unroll
            for (int s = 0; s < 32; s++)
                v[s] = p[(long)(8 * s) * IN_DIM];     // warp: 128B coalesced per load
        } else {
            const bool kok = (kc + kk < IN_DIM);
#pragma unroll
            for (int s = 0; s < 32; s++) {
                int r = row0 + rbase + 8 * s;
                v[s] = (r < N_NODES && kok) ? p[(long)(8 * s) * IN_DIM] : 0.f;
            }
        }
    };
    auto prefW = [&](int c) {
        const int kc = c * KC;
#pragma unroll
        for (int s = 0; s < 2; s++) {
            int flat = t + 256 * s;
            int k = flat >> 4, j = flat & 15;
            wv[s] = (kc + k < IN_DIM) ? W1[(kc + k) * HID + j] : 0.f;
        }
    };

    prefA(0); prefW(0);

    for (int c = 0; c < NCHUNK; c++) {
        // store staged regs -> smem (STS stride 33 across lanes: conflict-free)
#pragma unroll
        for (int s = 0; s < 32; s++) As[rbase + 8 * s][kk] = v[s];
#pragma unroll
        for (int s = 0; s < 2; s++) {
            int flat = t + 256 * s;
            int k = flat >> 4, j = flat & 15;
            Ws[k][j] = wv[s];
        }
        __syncthreads();

        // launch next chunk's loads; they fly during compute below
        if (c + 1 < NCHUNK) { prefA(c + 1); prefW(c + 1); }

        // compute chunk c from smem
#pragma unroll 8
        for (int k = 0; k < KC; k++) {
            const ulonglong2* wp = (const ulonglong2*)&Ws[k][0];
            ulonglong2 wa = wp[0], wb = wp[1], wc = wp[2], wd = wp[3];
            float a = As[t][k];
            ull ap = pack2(a, a);
            ffma2(acc[0], ap, wa.x); ffma2(acc[1], ap, wa.y);
            ffma2(acc[2], ap, wb.x); ffma2(acc[3], ap, wb.y);
            ffma2(acc[4], ap, wc.x); ffma2(acc[5], ap, wc.y);
            ffma2(acc[6], ap, wd.x); ffma2(acc[7], ap, wd.y);
        }
        __syncthreads();
    }

    int r = row0 + t;
    if (r < N_NODES) {
        ulonglong2* d = (ulonglong2*)&g_XW1[r * HID];
        d[0] = make_ulonglong2(acc[0], acc[1]);
        d[1] = make_ulonglong2(acc[2], acc[3]);
        d[2] = make_ulonglong2(acc[4], acc[5]);
        d[3] = make_ulonglong2(acc[6], acc[7]);
    }
}

__global__ void __launch_bounds__(1024) scan2_kernel() {
    __shared__ int s[1024];
    int t = threadIdx.x;
    int x = (t < SCAN_BLOCKS) ? g_bsum[t] : 0;
    s[t] = x;
    __syncthreads();
#pragma unroll
    for (int d = 1; d < 1024; d <<= 1) {
        int y = (t >= d) ? s[t - d] : 0;
        __syncthreads();
        s[t] += y;
        __syncthreads();
    }
    if (t < SCAN_BLOCKS) g_boff[t] = s[t] - x;
}

__global__ void __launch_bounds__(256) scan3_kernel() {
    int i = blockIdx.x * 256 + threadIdx.x;
    if (i < N_NODES) {
        int v = g_rowptr[i] + g_boff[blockIdx.x];
        g_rowptr[i] = v;
        g_pos[i] = v;
    }
    if (i == 0) g_rowptr[N_NODES] = N_EDGES;
}

// -------- scatter edges into row-sorted packed array --------
__global__ void __launch_bounds__(256) scatter_kernel(const int*   __restrict__ erow,
                                                      const int*   __restrict__ ecol,
                                                      const float* __restrict__ evals) {
    int q = blockIdx.x * 256 + threadIdx.x;
    if (q >= N_EDGES / 4) return;
    int4   r4 = ((const int4*)erow)[q];
    int4   c4 = ((const int4*)ecol)[q];
    float4 v4 = ((const float4*)evals)[q];
    int   rr[4] = {r4.x, r4.y, r4.z, r4.w};
    int   cc[4] = {c4.x, c4.y, c4.z, c4.w};
    float vv[4] = {v4.x, v4.y, v4.z, v4.w};
#pragma unroll
    for (int i = 0; i < 4; i++) {
        int p = atomicAdd(&g_pos[rr[i]], 1);
        g_edge[p] = ((ull)__float_as_uint(vv[i]) << 32) | (unsigned)cc[i];
    }
}

// -------- SPMM1: warp per row, lanes 0-15 even edges / 16-31 odd, 4x unroll --------
__global__ void __launch_bounds__(256) spmm1_kernel() {
    int warp = (blockIdx.x * 256 + threadIdx.x) >> 5;
    if (warp >= N_NODES) return;
    int lane = threadIdx.x & 31;
    int half = lane >> 4;
    int dim  = lane & 15;

    int start = g_rowptr[warp];
    int end   = g_rowptr[warp + 1];

    float acc = 0.f;
    int i = start + half;
    for (; i + 6 < end; i += 8) {
        ull e0 = g_edge[i];
        ull e1 = g_edge[i + 2];
        ull e2 = g_edge[i + 4];
        ull e3 = g_edge[i + 6];
        int c0 = (int)(unsigned)e0;  float v0 = __uint_as_float((unsigned)(e0 >> 32));
        int c1 = (int)(unsigned)e1;  float v1 = __uint_as_float((unsigned)(e1 >> 32));
        int c2 = (int)(unsigned)e2;  float v2 = __uint_as_float((unsigned)(e2 >> 32));
        int c3 = (int)(unsigned)e3;  float v3 = __uint_as_float((unsigned)(e3 >> 32));
        float x0 = g_XW1[c0 * HID + dim];
        float x1 = g_XW1[c1 * HID + dim];
        float x2 = g_XW1[c2 * HID + dim];
        float x3 = g_XW1[c3 * HID + dim];
        acc = fmaf(v0, x0, acc);
        acc = fmaf(v1, x1, acc);
        acc = fmaf(v2, x2, acc);
        acc = fmaf(v3, x3, acc);
    }
    for (; i < end; i += 2) {
        ull e0 = g_edge[i];
        int c0 = (int)(unsigned)e0;  float v0 = __uint_as_float((unsigned)(e0 >> 32));
        acc = fmaf(v0, g_XW1[c0 * HID + dim], acc);
    }
    acc += __shfl_xor_sync(0xffffffff, acc, 16);
    if (half == 0) g_H[warp * HID + dim] = acc;
}

// -------- GEMM2  g_HW2 = relu(g_H + b1) @ W2, padded to 8 cols --------
__global__ void __launch_bounds__(256) gemm2_kernel(const float* __restrict__ b1,
                                                    const float* __restrict__ W2) {
    __shared__ float sW2[HID * OUTD];
    __shared__ float sb1[HID];
    int t = threadIdx.x;
    if (t < HID * OUTD) sW2[t] = W2[t];
    if (t < HID)        sb1[t] = b1[t];
    __syncthreads();

    int i = blockIdx.x * 256 + t;
    if (i >= N_NODES) return;

    const float4* hp = (const float4*)&g_H[i * HID];
    float h[16];
    *(float4*)&h[0]  = hp[0]; *(float4*)&h[4]  = hp[1];
    *(float4*)&h[8]  = hp[2]; *(float4*)&h[12] = hp[3];
#pragma unroll
    for (int j = 0; j < 16; j++) h[j] = fmaxf(h[j] + sb1[j], 0.f);

    float o[OUTP];
#pragma unroll
    for (int c = 0; c < OUTD; c++) {
        float s = 0.f;
#pragma unroll
        for (int j = 0; j < HID; j++) s = fmaf(h[j], sW2[j * OUTD + c], s);
        o[c] = s;
    }
    o[7] = 0.f;

    float4* d = (float4*)&g_HW2[i * OUTP];
    d[0] = *(float4*)&o[0];
    d[1] = *(float4*)&o[4];
}

// -------- SPMM2 + bias fused --------
__global__ void __launch_bounds__(256) spmm2_kernel(const float* __restrict__ b2,
                                                    float* __restrict__ out) {
    int warp = (blockIdx.x * 256 + threadIdx.x) >> 5;
    if (warp >= N_NODES) return;
    int lane = threadIdx.x & 31;
    int sub  = lane >> 3;
    int dim  = lane & 7;

    int start = g_rowptr[warp];
    int end   = g_rowptr[warp + 1];

    float acc = 0.f;
    int i = start + sub;
    for (; i + 12 < end; i += 16) {
        ull e0 = g_edge[i];
        ull e1 = g_edge[i + 4];
        ull e2 = g_edge[i + 8];
        ull e3 = g_edge[i + 12];
        int c0 = (int)(unsigned)e0;  float v0 = __uint_as_float((unsigned)(e0 >> 32));
        int c1 = (int)(unsigned)e1;  float v1 = __uint_as_float((unsigned)(e1 >> 32));
        int c2 = (int)(unsigned)e2;  float v2 = __uint_as_float((unsigned)(e2 >> 32));
        int c3 = (int)(unsigned)e3;  float v3 = __uint_as_float((unsigned)(e3 >> 32));
        float x0 = g_HW2[c0 * OUTP + dim];
        float x1 = g_HW2[c1 * OUTP + dim];
        float x2 = g_HW2[c2 * OUTP + dim];
        float x3 = g_HW2[c3 * OUTP + dim];
        acc = fmaf(v0, x0, acc);
        acc = fmaf(v1, x1, acc);
        acc = fmaf(v2, x2, acc);
        acc = fmaf(v3, x3, acc);
    }
    for (; i < end; i += 4) {
        ull e0 = g_edge[i];
        int c0 = (int)(unsigned)e0;  float v0 = __uint_as_float((unsigned)(e0 >> 32));
        acc = fmaf(v0, g_HW2[c0 * OUTP + dim], acc);
    }
    acc += __shfl_xor_sync(0xffffffff, acc, 8);
    acc += __shfl_xor_sync(0xffffffff, acc, 16);
    if (lane < OUTD) out[warp * OUTD + lane] = acc + b2[lane];
}

extern "C" void kernel_launch(void* const* d_in, const int* in_sizes, int n_in,
                              void* d_out, int out_size) {
    const float* feature = (const float*)d_in[0];
    const int*   erow    = (const int*)  d_in[1];
    const int*   ecol    = (const int*)  d_in[2];
    const float* evals   = (const float*)d_in[3];
    const float* W1      = (const float*)d_in[4];
    const float* b1      = (const float*)d_in[5];
    const float* W2      = (const float*)d_in[6];
    const float* b2      = (const float*)d_in[7];
    float* out = (float*)d_out;

    int quad_blocks = (N_EDGES / 4 + 255) / 256;           // 6250
    int node_blocks = (N_NODES + 255) / 256;               // 782
    int warp_blocks = (N_NODES * 32 + 255) / 256;          // 25000

    // order keeps gemm1 at launch index 3 -> the kernel ncu captures
    zero_kernel<<<node_blocks, 256>>>();                   // 0
    count_kernel<<<quad_blocks, 256>>>(erow);              // 1
    scan1_kernel<<<SCAN_BLOCKS, 256>>>();                  // 2
    gemm1_kernel<<<node_blocks, 256>>>(feature, W1);       // 3  <- profiled
    scan2_kernel<<<1, 1024>>>();                           // 4
    scan3_kernel<<<SCAN_BLOCKS, 256>>>();                  // 5
    scatter_kernel<<<quad_blocks, 256>>>(erow, ecol, evals);
    spmm1_kernel<<<warp_blocks, 256>>>();
    gemm2_kernel<<<node_blocks, 256>>>(b1, W2);
    spmm2_kernel<<<warp_blocks, 256>>>(b2, out);
}